// round 1
// baseline (speedup 1.0000x reference)
#include <cuda_runtime.h>
#include <cuda_bf16.h>

// Problem dims
#define A_DIM 384
#define F_DIM 128
#define C_DIM 32
#define H_DIM 512   // F*NT
#define EPS 1e-5f

// Main-kernel tiling
#define BM 64
#define TM 4
#define TN 8
#define NTHREADS 256
#define FP (F_DIM + 4)   // padded row stride (floats), keeps 16B alignment

// ---------------------------------------------------------------------------
// Device scratch (no allocations allowed)
// ---------------------------------------------------------------------------
__device__ float g_left[A_DIM * C_DIM];
__device__ float g_right[A_DIM * C_DIM];
__device__ float g_M[A_DIM * C_DIM * F_DIM];   // M[a][d][f] = sum_c left[a,c]*w_out[c*32+d, f]

// ---------------------------------------------------------------------------
// Kernel 1: layernorm(node_vec) -> left/right projections (masked)
// 384 blocks x 128 threads
// ---------------------------------------------------------------------------
__global__ void k_node(const float* __restrict__ node_vec,
                       const float* __restrict__ node_mask,
                       const float* __restrict__ ln_scale,
                       const float* __restrict__ ln_bias,
                       const float* __restrict__ w_left,
                       const float* __restrict__ b_left,
                       const float* __restrict__ w_right,
                       const float* __restrict__ b_right) {
    int a = blockIdx.x;
    int t = threadIdx.x;   // 0..127
    __shared__ float act[F_DIM];
    __shared__ float red[4];

    float x = node_vec[a * F_DIM + t];
    // mean
    float s = x;
    #pragma unroll
    for (int o = 16; o; o >>= 1) s += __shfl_xor_sync(~0u, s, o);
    if ((t & 31) == 0) red[t >> 5] = s;
    __syncthreads();
    float mu = (red[0] + red[1] + red[2] + red[3]) * (1.0f / F_DIM);
    __syncthreads();
    // var (two-pass, matches reference)
    float d = x - mu;
    float s2 = d * d;
    #pragma unroll
    for (int o = 16; o; o >>= 1) s2 += __shfl_xor_sync(~0u, s2, o);
    if ((t & 31) == 0) red[t >> 5] = s2;
    __syncthreads();
    float var = (red[0] + red[1] + red[2] + red[3]) * (1.0f / F_DIM);
    float rstd = rsqrtf(var + EPS);
    act[t] = d * rstd * ln_scale[t] + ln_bias[t];
    __syncthreads();

    float nm = node_mask[a];
    if (t < C_DIM) {
        float acc = b_left[t];
        #pragma unroll 8
        for (int f = 0; f < F_DIM; f++) acc += act[f] * w_left[f * C_DIM + t];
        g_left[a * C_DIM + t] = acc * nm;
    } else if (t < 2 * C_DIM) {
        int c = t - C_DIM;
        float acc = b_right[c];
        #pragma unroll 8
        for (int f = 0; f < F_DIM; f++) acc += act[f] * w_right[f * C_DIM + c];
        g_right[a * C_DIM + c] = acc * nm;
    }
}

// ---------------------------------------------------------------------------
// Kernel 2: M[a][d][f] = sum_c left[a,c] * w_out[(c*32+d)*128 + f]
// 384 blocks x 128 threads (thread = f)
// ---------------------------------------------------------------------------
__global__ void k_precompute_M(const float* __restrict__ w_out) {
    int a = blockIdx.x;
    int f = threadIdx.x;   // 0..127
    __shared__ float lft[C_DIM];
    if (f < C_DIM) lft[f] = g_left[a * C_DIM + f];
    __syncthreads();

    #pragma unroll 4
    for (int d = 0; d < C_DIM; d++) {
        float acc = 0.0f;
        #pragma unroll 8
        for (int c = 0; c < C_DIM; c++)
            acc += lft[c] * w_out[(c * C_DIM + d) * F_DIM + f];
        g_M[(a * C_DIM + d) * F_DIM + f] = acc;
    }
}

// ---------------------------------------------------------------------------
// Kernel 3: fused main kernel.
// grid = (A/BM, A): blockIdx.y = a, blockIdx.x = b tile (64 rows).
// ---------------------------------------------------------------------------
struct SmemMain {
    float m_a[C_DIM][F_DIM];        // 16 KB, M[a]
    float right_s[BM][C_DIM + 1];   // 8.25 KB
    float e_s[BM][FP];              // 33 KB  (edge + op, kept for residual)
    float ln_s[BM][FP];             // 33 KB
    float h_s[BM][FP];              // 33 KB
    float wbuf[F_DIM][FP];          // 66 KB  (shared W1/W2 chunk buffer)
};
#define SMEM_MAIN_BYTES (sizeof(SmemMain))

__device__ __forceinline__ void gemm_tile_k128(const float* __restrict__ A_s,
                                               const float* __restrict__ B_s,
                                               int r0, int c0,
                                               float acc[TM][TN]) {
    // A_s: [BM][FP], B_s: [128][FP]; acc += A[r0..r0+3][0:128] @ B[0:128][c0..c0+7]
    for (int k = 0; k < 128; k += 4) {
        float4 a4[TM];
        #pragma unroll
        for (int i = 0; i < TM; i++)
            a4[i] = *reinterpret_cast<const float4*>(A_s + (r0 + i) * FP + k);
        #pragma unroll
        for (int kk = 0; kk < 4; kk++) {
            float4 bv0 = *reinterpret_cast<const float4*>(B_s + (k + kk) * FP + c0);
            float4 bv1 = *reinterpret_cast<const float4*>(B_s + (k + kk) * FP + c0 + 4);
            #pragma unroll
            for (int i = 0; i < TM; i++) {
                float av = (kk == 0) ? a4[i].x : (kk == 1) ? a4[i].y
                         : (kk == 2) ? a4[i].z : a4[i].w;
                acc[i][0] += av * bv0.x; acc[i][1] += av * bv0.y;
                acc[i][2] += av * bv0.z; acc[i][3] += av * bv0.w;
                acc[i][4] += av * bv1.x; acc[i][5] += av * bv1.y;
                acc[i][6] += av * bv1.z; acc[i][7] += av * bv1.w;
            }
        }
    }
}

__global__ __launch_bounds__(NTHREADS, 1)
void k_main(const float* __restrict__ edge_vec,
            const float* __restrict__ b_out,
            const float* __restrict__ tr_scale,
            const float* __restrict__ tr_bias,
            const float* __restrict__ w_t1,
            const float* __restrict__ b_t1,
            const float* __restrict__ w_t2,
            const float* __restrict__ b_t2,
            float* __restrict__ out) {
    extern __shared__ char smem_raw[];
    SmemMain& sm = *reinterpret_cast<SmemMain*>(smem_raw);

    const int a  = blockIdx.y;
    const int b0 = blockIdx.x * BM;
    const int tid = threadIdx.x;
    const int ty = tid >> 4, tx = tid & 15;
    const int r0 = ty * TM, c0 = tx * TN;

    // ---- load M[a] and right rows ----
    for (int idx = tid; idx < C_DIM * F_DIM; idx += NTHREADS)
        sm.m_a[idx >> 7][idx & 127] = g_M[a * C_DIM * F_DIM + idx];
    for (int idx = tid; idx < BM * C_DIM; idx += NTHREADS)
        sm.right_s[idx >> 5][idx & 31] = g_right[b0 * C_DIM + idx];
    __syncthreads();

    // ---- e = right @ M_a + edge_vec + b_out ----
    {
        float acc[TM][TN];
        #pragma unroll
        for (int i = 0; i < TM; i++)
            #pragma unroll
            for (int j = 0; j < TN; j++) acc[i][j] = 0.0f;

        #pragma unroll
        for (int k = 0; k < C_DIM; k++) {
            float af[TM];
            #pragma unroll
            for (int i = 0; i < TM; i++) af[i] = sm.right_s[r0 + i][k];
            const float* brow = &sm.m_a[k][c0];
            float4 bv0 = *reinterpret_cast<const float4*>(brow);
            float4 bv1 = *reinterpret_cast<const float4*>(brow + 4);
            #pragma unroll
            for (int i = 0; i < TM; i++) {
                acc[i][0] += af[i] * bv0.x; acc[i][1] += af[i] * bv0.y;
                acc[i][2] += af[i] * bv0.z; acc[i][3] += af[i] * bv0.w;
                acc[i][4] += af[i] * bv1.x; acc[i][5] += af[i] * bv1.y;
                acc[i][6] += af[i] * bv1.z; acc[i][7] += af[i] * bv1.w;
            }
        }
        const float* ev = edge_vec + ((long)a * A_DIM + b0) * F_DIM;
        float bo[TN];
        #pragma unroll
        for (int j = 0; j < TN; j++) bo[j] = b_out[c0 + j];
        #pragma unroll
        for (int i = 0; i < TM; i++) {
            float4 e0 = *reinterpret_cast<const float4*>(ev + (r0 + i) * F_DIM + c0);
            float4 e1 = *reinterpret_cast<const float4*>(ev + (r0 + i) * F_DIM + c0 + 4);
            sm.e_s[r0 + i][c0 + 0] = acc[i][0] + e0.x + bo[0];
            sm.e_s[r0 + i][c0 + 1] = acc[i][1] + e0.y + bo[1];
            sm.e_s[r0 + i][c0 + 2] = acc[i][2] + e0.z + bo[2];
            sm.e_s[r0 + i][c0 + 3] = acc[i][3] + e0.w + bo[3];
            sm.e_s[r0 + i][c0 + 4] = acc[i][4] + e1.x + bo[4];
            sm.e_s[r0 + i][c0 + 5] = acc[i][5] + e1.y + bo[5];
            sm.e_s[r0 + i][c0 + 6] = acc[i][6] + e1.z + bo[6];
            sm.e_s[r0 + i][c0 + 7] = acc[i][7] + e1.w + bo[7];
        }
    }
    __syncthreads();

    // ---- layernorm rows of e -> ln_s (4 threads per row, two-pass) ----
    {
        const int row = tid >> 2;
        const int q = tid & 3;
        const int f0 = q * 32;
        float s = 0.0f;
        #pragma unroll 8
        for (int f = f0; f < f0 + 32; f++) s += sm.e_s[row][f];
        s += __shfl_xor_sync(~0u, s, 1);
        s += __shfl_xor_sync(~0u, s, 2);
        float mu = s * (1.0f / F_DIM);
        float v = 0.0f;
        #pragma unroll 8
        for (int f = f0; f < f0 + 32; f++) {
            float d = sm.e_s[row][f] - mu;
            v += d * d;
        }
        v += __shfl_xor_sync(~0u, v, 1);
        v += __shfl_xor_sync(~0u, v, 2);
        float rstd = rsqrtf(v * (1.0f / F_DIM) + EPS);
        #pragma unroll 8
        for (int f = f0; f < f0 + 32; f++)
            sm.ln_s[row][f] = (sm.e_s[row][f] - mu) * rstd * tr_scale[f] + tr_bias[f];
    }
    __syncthreads();

    // ---- transition MLP in 4 j-chunks of 128 ----
    float oacc[TM][TN];
    #pragma unroll
    for (int i = 0; i < TM; i++)
        #pragma unroll
        for (int j = 0; j < TN; j++) oacc[i][j] = 0.0f;

    for (int jc = 0; jc < 4; jc++) {
        // load W1 chunk [128][128]
        for (int idx = tid; idx < F_DIM * F_DIM; idx += NTHREADS) {
            int k = idx >> 7, j = idx & 127;
            sm.wbuf[k][j] = w_t1[k * H_DIM + jc * F_DIM + j];
        }
        __syncthreads();

        float hacc[TM][TN];
        #pragma unroll
        for (int i = 0; i < TM; i++)
            #pragma unroll
            for (int j = 0; j < TN; j++) hacc[i][j] = 0.0f;
        gemm_tile_k128(&sm.ln_s[0][0], &sm.wbuf[0][0], r0, c0, hacc);

        float b1[TN];
        #pragma unroll
        for (int j = 0; j < TN; j++) b1[j] = b_t1[jc * F_DIM + c0 + j];
        #pragma unroll
        for (int i = 0; i < TM; i++)
            #pragma unroll
            for (int j = 0; j < TN; j++)
                sm.h_s[r0 + i][c0 + j] = fmaxf(hacc[i][j] + b1[j], 0.0f);
        __syncthreads();

        // load W2 chunk [128][128]
        for (int idx = tid; idx < F_DIM * F_DIM; idx += NTHREADS) {
            int k = idx >> 7, j = idx & 127;
            sm.wbuf[k][j] = w_t2[(jc * F_DIM + k) * F_DIM + j];
        }
        __syncthreads();

        gemm_tile_k128(&sm.h_s[0][0], &sm.wbuf[0][0], r0, c0, oacc);
        __syncthreads();   // before next chunk overwrites wbuf
    }

    // ---- epilogue: out = e + t2 + b_t2 ----
    float* op = out + ((long)a * A_DIM + b0) * F_DIM;
    float b2[TN];
    #pragma unroll
    for (int j = 0; j < TN; j++) b2[j] = b_t2[c0 + j];
    #pragma unroll
    for (int i = 0; i < TM; i++) {
        float4 o0, o1;
        o0.x = sm.e_s[r0 + i][c0 + 0] + oacc[i][0] + b2[0];
        o0.y = sm.e_s[r0 + i][c0 + 1] + oacc[i][1] + b2[1];
        o0.z = sm.e_s[r0 + i][c0 + 2] + oacc[i][2] + b2[2];
        o0.w = sm.e_s[r0 + i][c0 + 3] + oacc[i][3] + b2[3];
        o1.x = sm.e_s[r0 + i][c0 + 4] + oacc[i][4] + b2[4];
        o1.y = sm.e_s[r0 + i][c0 + 5] + oacc[i][5] + b2[5];
        o1.z = sm.e_s[r0 + i][c0 + 6] + oacc[i][6] + b2[6];
        o1.w = sm.e_s[r0 + i][c0 + 7] + oacc[i][7] + b2[7];
        *reinterpret_cast<float4*>(op + (r0 + i) * F_DIM + c0) = o0;
        *reinterpret_cast<float4*>(op + (r0 + i) * F_DIM + c0 + 4) = o1;
    }
}

// ---------------------------------------------------------------------------
// Launch
// ---------------------------------------------------------------------------
extern "C" void kernel_launch(void* const* d_in, const int* in_sizes, int n_in,
                              void* d_out, int out_size) {
    const float* node_vec    = (const float*)d_in[0];
    const float* edge_vec    = (const float*)d_in[1];
    const float* node_mask   = (const float*)d_in[2];
    // d_in[3] = edge_mask (unused by reference)
    const float* op_ln_scale = (const float*)d_in[4];
    const float* op_ln_bias  = (const float*)d_in[5];
    const float* w_left      = (const float*)d_in[6];
    const float* b_left      = (const float*)d_in[7];
    const float* w_right     = (const float*)d_in[8];
    const float* b_right     = (const float*)d_in[9];
    const float* w_out       = (const float*)d_in[10];
    const float* b_out       = (const float*)d_in[11];
    const float* tr_ln_scale = (const float*)d_in[12];
    const float* tr_ln_bias  = (const float*)d_in[13];
    const float* w_t1        = (const float*)d_in[14];
    const float* b_t1        = (const float*)d_in[15];
    const float* w_t2        = (const float*)d_in[16];
    const float* b_t2        = (const float*)d_in[17];
    float* out = (float*)d_out;

    static bool attr_set = false;
    if (!attr_set) {
        cudaFuncSetAttribute(k_main, cudaFuncAttributeMaxDynamicSharedMemorySize,
                             (int)SMEM_MAIN_BYTES);
        attr_set = true;
    }

    k_node<<<A_DIM, F_DIM>>>(node_vec, node_mask, op_ln_scale, op_ln_bias,
                             w_left, b_left, w_right, b_right);
    k_precompute_M<<<A_DIM, F_DIM>>>(w_out);
    k_main<<<dim3(A_DIM / BM, A_DIM), NTHREADS, SMEM_MAIN_BYTES>>>(
        edge_vec, b_out, tr_ln_scale, tr_ln_bias,
        w_t1, b_t1, w_t2, b_t2, out);
}

// round 3
// speedup vs baseline: 3.8263x; 3.8263x over previous
#include <cuda_runtime.h>
#include <cuda_bf16.h>
#include <cstdint>

#define A_DIM 384
#define F_DIM 128
#define C_DIM 32
#define H_DIM 512
#define EPS 1e-5f
#define BM 128
#define NTHREADS 256

// ---- smem layout in floats ----
#define LNOFF 0
#define HOFF  16896          // 128*132
#define WOFF  33792
#define BOFF  50688          // scale[128] bias[128] b1[512] b2[128] bout[128]
#define SMEM_FLOATS 51712
#define SMEM_BYTES  (SMEM_FLOATS * 4)
#define LDS_STRIDE 132

// ---- device scratch ----
__device__ float g_left[A_DIM * C_DIM];
__device__ float g_right[A_DIM * C_DIM];
__device__ float g_M[A_DIM * C_DIM * F_DIM];   // M[a][d][f]

__device__ __forceinline__ uint32_t f2tf32(float x) {
    uint32_t r;
    asm("cvt.rna.tf32.f32 %0, %1;" : "=r"(r) : "f"(x));
    return r;
}
__device__ __forceinline__ float f2tf32f(float x) {
    return __uint_as_float(f2tf32(x));
}

__device__ __forceinline__ void mma_tf32(float c[4], uint32_t a0, uint32_t a1,
                                         uint32_t a2, uint32_t a3,
                                         uint32_t b0, uint32_t b1) {
    asm volatile(
        "mma.sync.aligned.m16n8k8.row.col.f32.tf32.tf32.f32 "
        "{%0,%1,%2,%3}, {%4,%5,%6,%7}, {%8,%9}, {%0,%1,%2,%3};"
        : "+f"(c[0]), "+f"(c[1]), "+f"(c[2]), "+f"(c[3])
        : "r"(a0), "r"(a1), "r"(a2), "r"(a3), "r"(b0), "r"(b1));
}

// ---------------------------------------------------------------------------
// Kernel 1: layernorm(node_vec) -> left/right projections (masked)
// ---------------------------------------------------------------------------
__global__ void k_node(const float* __restrict__ node_vec,
                       const float* __restrict__ node_mask,
                       const float* __restrict__ ln_scale,
                       const float* __restrict__ ln_bias,
                       const float* __restrict__ w_left,
                       const float* __restrict__ b_left,
                       const float* __restrict__ w_right,
                       const float* __restrict__ b_right) {
    int a = blockIdx.x;
    int t = threadIdx.x;
    __shared__ float act[F_DIM];
    __shared__ float red[4];

    float x = node_vec[a * F_DIM + t];
    float s = x;
    #pragma unroll
    for (int o = 16; o; o >>= 1) s += __shfl_xor_sync(~0u, s, o);
    if ((t & 31) == 0) red[t >> 5] = s;
    __syncthreads();
    float mu = (red[0] + red[1] + red[2] + red[3]) * (1.0f / F_DIM);
    __syncthreads();
    float d = x - mu;
    float s2 = d * d;
    #pragma unroll
    for (int o = 16; o; o >>= 1) s2 += __shfl_xor_sync(~0u, s2, o);
    if ((t & 31) == 0) red[t >> 5] = s2;
    __syncthreads();
    float var = (red[0] + red[1] + red[2] + red[3]) * (1.0f / F_DIM);
    float rstd = rsqrtf(var + EPS);
    act[t] = d * rstd * ln_scale[t] + ln_bias[t];
    __syncthreads();

    float nm = node_mask[a];
    if (t < C_DIM) {
        float acc = b_left[t];
        #pragma unroll 8
        for (int f = 0; f < F_DIM; f++) acc += act[f] * w_left[f * C_DIM + t];
        g_left[a * C_DIM + t] = acc * nm;
    } else if (t < 2 * C_DIM) {
        int c = t - C_DIM;
        float acc = b_right[c];
        #pragma unroll 8
        for (int f = 0; f < F_DIM; f++) acc += act[f] * w_right[f * C_DIM + c];
        g_right[a * C_DIM + c] = acc * nm;
    }
}

// ---------------------------------------------------------------------------
// Kernel 2: M[a][d][f] = sum_c left[a,c] * w_out[(c*32+d)*128 + f]
// ---------------------------------------------------------------------------
__global__ void k_precompute_M(const float* __restrict__ w_out) {
    int a = blockIdx.x;
    int f = threadIdx.x;
    __shared__ float lft[C_DIM];
    if (f < C_DIM) lft[f] = g_left[a * C_DIM + f];
    __syncthreads();

    #pragma unroll 4
    for (int d = 0; d < C_DIM; d++) {
        float acc = 0.0f;
        #pragma unroll 8
        for (int c = 0; c < C_DIM; c++)
            acc += lft[c] * w_out[(c * C_DIM + d) * F_DIM + f];
        g_M[(a * C_DIM + d) * F_DIM + f] = acc;
    }
}

// ---------------------------------------------------------------------------
// 128x128x128 tf32 warp-mma GEMM: acc += A[128,128] @ W[128,128]
// A at S[aoff] (stride 132), W at S[WOFF] (stride 132, k-major).
// Warp tile 64x32: m0 = (wid>>2)*64, n0 = (wid&3)*32.
// ---------------------------------------------------------------------------
__device__ __forceinline__ void gemm128_tf32(const float* __restrict__ S,
                                             int aoff, int m0, int n0,
                                             int g, int tig,
                                             float acc[4][4][4]) {
    const float* As = S + aoff;
    const float* Ws = S + WOFF;
    #pragma unroll
    for (int ks = 0; ks < 16; ks++) {
        const int k0 = ks * 8;
        uint32_t a[4][4];
        #pragma unroll
        for (int mt = 0; mt < 4; mt++) {
            const int r = m0 + mt * 16 + g;
            a[mt][0] = __float_as_uint(As[r * LDS_STRIDE + k0 + tig]);
            a[mt][1] = __float_as_uint(As[(r + 8) * LDS_STRIDE + k0 + tig]);
            a[mt][2] = __float_as_uint(As[r * LDS_STRIDE + k0 + tig + 4]);
            a[mt][3] = __float_as_uint(As[(r + 8) * LDS_STRIDE + k0 + tig + 4]);
        }
        uint32_t b[4][2];
        #pragma unroll
        for (int nt = 0; nt < 4; nt++) {
            const int c = n0 + nt * 8 + g;
            b[nt][0] = __float_as_uint(Ws[(k0 + tig) * LDS_STRIDE + c]);
            b[nt][1] = __float_as_uint(Ws[(k0 + tig + 4) * LDS_STRIDE + c]);
        }
        #pragma unroll
        for (int mt = 0; mt < 4; mt++)
            #pragma unroll
            for (int nt = 0; nt < 4; nt++)
                mma_tf32(acc[mt][nt], a[mt][0], a[mt][1], a[mt][2], a[mt][3],
                         b[nt][0], b[nt][1]);
    }
}

// weight chunk loader: S[WOFF + row*132 + q*4 ..] = cvt(src[row*ld + col0 + q*4 ..])
__device__ __forceinline__ void load_w(float* __restrict__ S,
                                       const float* __restrict__ src,
                                       int ld, int col0, int tid) {
    #pragma unroll
    for (int idx = tid; idx < 128 * 32; idx += NTHREADS) {
        const int row = idx >> 5, q = idx & 31;
        float4 v = *reinterpret_cast<const float4*>(src + row * ld + col0 + q * 4);
        float4 t;
        t.x = f2tf32f(v.x); t.y = f2tf32f(v.y);
        t.z = f2tf32f(v.z); t.w = f2tf32f(v.w);
        *reinterpret_cast<float4*>(S + WOFF + row * LDS_STRIDE + q * 4) = t;
    }
}

// ---------------------------------------------------------------------------
// Kernel 3: fused main kernel (tf32 mma.sync). grid = (3, 384), 256 threads.
// ---------------------------------------------------------------------------
__global__ __launch_bounds__(NTHREADS, 1)
void k_main(const float* __restrict__ edge_vec,
            const float* __restrict__ b_out,
            const float* __restrict__ tr_scale,
            const float* __restrict__ tr_bias,
            const float* __restrict__ w_t1,
            const float* __restrict__ b_t1,
            const float* __restrict__ w_t2,
            const float* __restrict__ b_t2,
            float* __restrict__ out) {
    extern __shared__ float S[];
    const int tid = threadIdx.x;
    const int wid = tid >> 5;
    const int lane = tid & 31;
    const int g = lane >> 2;        // groupID
    const int tig = lane & 3;       // thread in group
    const int a = blockIdx.y;
    const int bb = blockIdx.x * BM;

    float* s_scale = S + BOFF;
    float* s_bias  = S + BOFF + 128;
    float* s_b1    = S + BOFF + 256;
    float* s_b2    = S + BOFF + 768;
    float* s_bout  = S + BOFF + 896;

    // ---- stage biases, m_a (overlay in W region), right_s ----
    for (int i = tid; i < F_DIM; i += NTHREADS) {
        s_scale[i] = tr_scale[i];
        s_bias[i]  = tr_bias[i];
        s_b2[i]    = b_t2[i];
        s_bout[i]  = b_out[i];
    }
    for (int i = tid; i < H_DIM; i += NTHREADS) s_b1[i] = b_t1[i];
    for (int idx = tid; idx < C_DIM * F_DIM; idx += NTHREADS)
        S[WOFF + idx] = g_M[a * C_DIM * F_DIM + idx];          // m_a[d][f]
    for (int idx = tid; idx < BM * C_DIM; idx += NTHREADS) {
        int r = idx >> 5, c = idx & 31;
        S[WOFF + 4096 + r * 33 + c] = g_right[(bb + r) * C_DIM + c];
    }
    __syncthreads();

    // ---- e = right @ M_a + edge + b_out  (exact fp32), -> gmem out + s_h ----
    {
        const int r0 = (tid >> 4) * 8;
        const int c0 = (tid & 15) * 8;
        float acc[8][8];
        #pragma unroll
        for (int i = 0; i < 8; i++)
            #pragma unroll
            for (int j = 0; j < 8; j++) acc[i][j] = 0.0f;

        #pragma unroll 4
        for (int k = 0; k < C_DIM; k++) {
            float4 bv0 = *reinterpret_cast<const float4*>(S + WOFF + k * 128 + c0);
            float4 bv1 = *reinterpret_cast<const float4*>(S + WOFF + k * 128 + c0 + 4);
            #pragma unroll
            for (int i = 0; i < 8; i++) {
                float av = S[WOFF + 4096 + (r0 + i) * 33 + k];
                acc[i][0] += av * bv0.x; acc[i][1] += av * bv0.y;
                acc[i][2] += av * bv0.z; acc[i][3] += av * bv0.w;
                acc[i][4] += av * bv1.x; acc[i][5] += av * bv1.y;
                acc[i][6] += av * bv1.z; acc[i][7] += av * bv1.w;
            }
        }
        const float* ep = edge_vec + ((long)(a * A_DIM) + bb) * F_DIM;
        float* op = out + ((long)(a * A_DIM) + bb) * F_DIM;
        #pragma unroll
        for (int i = 0; i < 8; i++) {
            const int r = r0 + i;
            #pragma unroll
            for (int jq = 0; jq < 2; jq++) {
                float4 e4 = *reinterpret_cast<const float4*>(ep + r * F_DIM + c0 + jq * 4);
                float4 o;
                o.x = acc[i][jq*4+0] + e4.x + s_bout[c0 + jq*4 + 0];
                o.y = acc[i][jq*4+1] + e4.y + s_bout[c0 + jq*4 + 1];
                o.z = acc[i][jq*4+2] + e4.z + s_bout[c0 + jq*4 + 2];
                o.w = acc[i][jq*4+3] + e4.w + s_bout[c0 + jq*4 + 3];
                *reinterpret_cast<float4*>(op + r * F_DIM + c0 + jq * 4) = o;
                *reinterpret_cast<float4*>(S + HOFF + r * LDS_STRIDE + c0 + jq * 4) = o;
            }
        }
    }
    __syncthreads();

    // ---- layernorm rows of e (from s_h) -> s_ln (tf32 converted) ----
    {
        const int row = tid >> 1;
        const int half = tid & 1;
        const float* er = S + HOFF + row * LDS_STRIDE + half * 64;
        float sum = 0.0f, sq = 0.0f;
        #pragma unroll
        for (int q = 0; q < 16; q++) {
            float4 v = *reinterpret_cast<const float4*>(er + q * 4);
            sum += v.x + v.y + v.z + v.w;
            sq  += v.x*v.x + v.y*v.y + v.z*v.z + v.w*v.w;
        }
        sum += __shfl_xor_sync(~0u, sum, 1);
        sq  += __shfl_xor_sync(~0u, sq, 1);
        float mu = sum * (1.0f / F_DIM);
        float var = sq * (1.0f / F_DIM) - mu * mu;
        float rstd = rsqrtf(var + EPS);
        #pragma unroll
        for (int q = 0; q < 16; q++) {
            float4 v = *reinterpret_cast<const float4*>(er + q * 4);
            const int c = half * 64 + q * 4;
            float4 l;
            l.x = f2tf32f((v.x - mu) * rstd * s_scale[c+0] + s_bias[c+0]);
            l.y = f2tf32f((v.y - mu) * rstd * s_scale[c+1] + s_bias[c+1]);
            l.z = f2tf32f((v.z - mu) * rstd * s_scale[c+2] + s_bias[c+2]);
            l.w = f2tf32f((v.w - mu) * rstd * s_scale[c+3] + s_bias[c+3]);
            *reinterpret_cast<float4*>(S + LNOFF + row * LDS_STRIDE + c) = l;
        }
    }
    __syncthreads();

    // ---- transition MLP: 4 j-chunks of 128 ----
    const int m0 = (wid >> 2) * 64;
    const int n0 = (wid & 3) * 32;

    float oacc[4][4][4];
    #pragma unroll
    for (int mt = 0; mt < 4; mt++)
        #pragma unroll
        for (int nt = 0; nt < 4; nt++)
            #pragma unroll
            for (int q = 0; q < 4; q++) oacc[mt][nt][q] = 0.0f;

    for (int jc = 0; jc < 4; jc++) {
        // W1 chunk -> s_w
        load_w(S, w_t1, H_DIM, jc * 128, tid);
        __syncthreads();

        // GEMM1: H = ln @ W1c
        float hacc[4][4][4];
        #pragma unroll
        for (int mt = 0; mt < 4; mt++)
            #pragma unroll
            for (int nt = 0; nt < 4; nt++)
                #pragma unroll
                for (int q = 0; q < 4; q++) hacc[mt][nt][q] = 0.0f;
        gemm128_tf32(S, LNOFF, m0, n0, g, tig, hacc);
        __syncthreads();

        // h = relu(H + b1) -> s_h (tf32); and stage W2 chunk -> s_w
        #pragma unroll
        for (int mt = 0; mt < 4; mt++) {
            const int r = m0 + mt * 16 + g;
            #pragma unroll
            for (int nt = 0; nt < 4; nt++) {
                const int c = n0 + nt * 8 + 2 * tig;
                const float bj0 = s_b1[jc * 128 + c];
                const float bj1 = s_b1[jc * 128 + c + 1];
                float2 h0, h1;
                h0.x = f2tf32f(fmaxf(hacc[mt][nt][0] + bj0, 0.0f));
                h0.y = f2tf32f(fmaxf(hacc[mt][nt][1] + bj1, 0.0f));
                h1.x = f2tf32f(fmaxf(hacc[mt][nt][2] + bj0, 0.0f));
                h1.y = f2tf32f(fmaxf(hacc[mt][nt][3] + bj1, 0.0f));
                *reinterpret_cast<float2*>(S + HOFF + r * LDS_STRIDE + c) = h0;
                *reinterpret_cast<float2*>(S + HOFF + (r + 8) * LDS_STRIDE + c) = h1;
            }
        }
        load_w(S, w_t2 + jc * 128 * F_DIM, F_DIM, 0, tid);
        __syncthreads();

        // GEMM2: O += h @ W2c
        gemm128_tf32(S, HOFF, m0, n0, g, tig, oacc);
        __syncthreads();
    }

    // ---- epilogue: out = e + O + b_t2 ----
    {
        float* op = out + ((long)(a * A_DIM) + bb) * F_DIM;
        #pragma unroll
        for (int mt = 0; mt < 4; mt++) {
            const int r = m0 + mt * 16 + g;
            #pragma unroll
            for (int nt = 0; nt < 4; nt++) {
                const int c = n0 + nt * 8 + 2 * tig;
                const float b20 = s_b2[c], b21 = s_b2[c + 1];
                float2 e0 = *reinterpret_cast<const float2*>(op + r * F_DIM + c);
                float2 e1 = *reinterpret_cast<const float2*>(op + (r + 8) * F_DIM + c);
                float2 o0, o1;
                o0.x = e0.x + oacc[mt][nt][0] + b20;
                o0.y = e0.y + oacc[mt][nt][1] + b21;
                o1.x = e1.x + oacc[mt][nt][2] + b20;
                o1.y = e1.y + oacc[mt][nt][3] + b21;
                *reinterpret_cast<float2*>(op + r * F_DIM + c) = o0;
                *reinterpret_cast<float2*>(op + (r + 8) * F_DIM + c) = o1;
            }
        }
    }
}

// ---------------------------------------------------------------------------
// Launch
// ---------------------------------------------------------------------------
extern "C" void kernel_launch(void* const* d_in, const int* in_sizes, int n_in,
                              void* d_out, int out_size) {
    const float* node_vec    = (const float*)d_in[0];
    const float* edge_vec    = (const float*)d_in[1];
    const float* node_mask   = (const float*)d_in[2];
    const float* op_ln_scale = (const float*)d_in[4];
    const float* op_ln_bias  = (const float*)d_in[5];
    const float* w_left      = (const float*)d_in[6];
    const float* b_left      = (const float*)d_in[7];
    const float* w_right     = (const float*)d_in[8];
    const float* b_right     = (const float*)d_in[9];
    const float* w_out       = (const float*)d_in[10];
    const float* b_out       = (const float*)d_in[11];
    const float* tr_ln_scale = (const float*)d_in[12];
    const float* tr_ln_bias  = (const float*)d_in[13];
    const float* w_t1        = (const float*)d_in[14];
    const float* b_t1        = (const float*)d_in[15];
    const float* w_t2        = (const float*)d_in[16];
    const float* b_t2        = (const float*)d_in[17];
    float* out = (float*)d_out;

    static bool attr_set = false;
    if (!attr_set) {
        cudaFuncSetAttribute(k_main, cudaFuncAttributeMaxDynamicSharedMemorySize,
                             (int)SMEM_BYTES);
        attr_set = true;
    }

    k_node<<<A_DIM, F_DIM>>>(node_vec, node_mask, op_ln_scale, op_ln_bias,
                             w_left, b_left, w_right, b_right);
    k_precompute_M<<<A_DIM, F_DIM>>>(w_out);
    k_main<<<dim3(A_DIM / BM, A_DIM), NTHREADS, SMEM_BYTES>>>(
        edge_vec, b_out, tr_ln_scale, tr_ln_bias,
        w_t1, b_t1, w_t2, b_t2, out);
}

// round 4
// speedup vs baseline: 3.8776x; 1.0134x over previous
#include <cuda_runtime.h>
#include <cuda_bf16.h>
#include <cstdint>

#define A_DIM 384
#define F_DIM 128
#define C_DIM 32
#define H_DIM 512
#define EPS 1e-5f
#define BM 128
#define NTHREADS 256

// ---- smem layout in floats ----
#define LNOFF 0                     // 128*132 = 16896
#define HOFF  16896                 // 128*132 = 16896
#define WOFF  33792                 // 2 bufs * 64*136 = 17408
#define WBUFSZ 8704                 // 64*136
#define BOFF  51200                 // scale128 bias128 b1 512 b2 128 bout128
#define SMEM_FLOATS 52224
#define SMEM_BYTES  (SMEM_FLOATS * 4)   // 208896
#define LDS_A 132
#define LDS_W 136

// ---- device scratch ----
__device__ float g_left[A_DIM * C_DIM];
__device__ float g_right[A_DIM * C_DIM];
__device__ float g_M[A_DIM * C_DIM * F_DIM];   // M[a][d][f]

__device__ __forceinline__ float f2tf32f(float x) {
    uint32_t r;
    asm("cvt.rna.tf32.f32 %0, %1;" : "=r"(r) : "f"(x));
    return __uint_as_float(r);
}

__device__ __forceinline__ void mma_tf32(float c[4], uint32_t a0, uint32_t a1,
                                         uint32_t a2, uint32_t a3,
                                         uint32_t b0, uint32_t b1) {
    asm volatile(
        "mma.sync.aligned.m16n8k8.row.col.f32.tf32.tf32.f32 "
        "{%0,%1,%2,%3}, {%4,%5,%6,%7}, {%8,%9}, {%0,%1,%2,%3};"
        : "+f"(c[0]), "+f"(c[1]), "+f"(c[2]), "+f"(c[3])
        : "r"(a0), "r"(a1), "r"(a2), "r"(a3), "r"(b0), "r"(b1));
}

__device__ __forceinline__ uint32_t smem_u32(const void* p) {
    uint32_t a;
    asm("{ .reg .u64 t; cvta.to.shared.u64 t, %1; cvt.u32.u64 %0, t; }" : "=r"(a) : "l"(p));
    return a;
}
__device__ __forceinline__ void cp_async16(uint32_t s, const void* g) {
    asm volatile("cp.async.ca.shared.global [%0], [%1], 16;" :: "r"(s), "l"(g));
}
#define CP_COMMIT() asm volatile("cp.async.commit_group;" ::: "memory")
#define CP_WAIT(n)  asm volatile("cp.async.wait_group %0;" :: "n"(n) : "memory")

// ---------------------------------------------------------------------------
// Kernel 1: layernorm(node_vec) -> left/right projections (masked)
// ---------------------------------------------------------------------------
__global__ void k_node(const float* __restrict__ node_vec,
                       const float* __restrict__ node_mask,
                       const float* __restrict__ ln_scale,
                       const float* __restrict__ ln_bias,
                       const float* __restrict__ w_left,
                       const float* __restrict__ b_left,
                       const float* __restrict__ w_right,
                       const float* __restrict__ b_right) {
    int a = blockIdx.x;
    int t = threadIdx.x;
    __shared__ float act[F_DIM];
    __shared__ float red[4];

    float x = node_vec[a * F_DIM + t];
    float s = x;
    #pragma unroll
    for (int o = 16; o; o >>= 1) s += __shfl_xor_sync(~0u, s, o);
    if ((t & 31) == 0) red[t >> 5] = s;
    __syncthreads();
    float mu = (red[0] + red[1] + red[2] + red[3]) * (1.0f / F_DIM);
    __syncthreads();
    float d = x - mu;
    float s2 = d * d;
    #pragma unroll
    for (int o = 16; o; o >>= 1) s2 += __shfl_xor_sync(~0u, s2, o);
    if ((t & 31) == 0) red[t >> 5] = s2;
    __syncthreads();
    float var = (red[0] + red[1] + red[2] + red[3]) * (1.0f / F_DIM);
    float rstd = rsqrtf(var + EPS);
    act[t] = d * rstd * ln_scale[t] + ln_bias[t];
    __syncthreads();

    float nm = node_mask[a];
    if (t < C_DIM) {
        float acc = b_left[t];
        #pragma unroll 8
        for (int f = 0; f < F_DIM; f++) acc += act[f] * w_left[f * C_DIM + t];
        g_left[a * C_DIM + t] = acc * nm;
    } else if (t < 2 * C_DIM) {
        int c = t - C_DIM;
        float acc = b_right[c];
        #pragma unroll 8
        for (int f = 0; f < F_DIM; f++) acc += act[f] * w_right[f * C_DIM + c];
        g_right[a * C_DIM + c] = acc * nm;
    }
}

// ---------------------------------------------------------------------------
// Kernel 2: M[a][d][f] = sum_c left[a,c] * w_out[(c*32+d)*128 + f]
// ---------------------------------------------------------------------------
__global__ void k_precompute_M(const float* __restrict__ w_out) {
    int a = blockIdx.x;
    int f = threadIdx.x;
    __shared__ float lft[C_DIM];
    if (f < C_DIM) lft[f] = g_left[a * C_DIM + f];
    __syncthreads();

    #pragma unroll 4
    for (int d = 0; d < C_DIM; d++) {
        float acc = 0.0f;
        #pragma unroll 8
        for (int c = 0; c < C_DIM; c++)
            acc += lft[c] * w_out[(c * C_DIM + d) * F_DIM + f];
        g_M[(a * C_DIM + d) * F_DIM + f] = acc;
    }
}

// ---------------------------------------------------------------------------
// GEMM over one 64-k half: acc += A[128, acol:acol+64] @ W[64,128]
// ---------------------------------------------------------------------------
__device__ __forceinline__ void gemm_half(const float* __restrict__ As, int acol,
                                          const float* __restrict__ Wb,
                                          int m0, int n0, int g, int tig,
                                          float acc[4][4][4]) {
    #pragma unroll
    for (int ks = 0; ks < 8; ks++) {
        const int k0 = ks * 8;
        uint32_t a[4][4];
        #pragma unroll
        for (int mt = 0; mt < 4; mt++) {
            const int r = m0 + mt * 16 + g;
            a[mt][0] = __float_as_uint(As[r * LDS_A + acol + k0 + tig]);
            a[mt][1] = __float_as_uint(As[(r + 8) * LDS_A + acol + k0 + tig]);
            a[mt][2] = __float_as_uint(As[r * LDS_A + acol + k0 + tig + 4]);
            a[mt][3] = __float_as_uint(As[(r + 8) * LDS_A + acol + k0 + tig + 4]);
        }
        uint32_t b[4][2];
        #pragma unroll
        for (int nt = 0; nt < 4; nt++) {
            const int c = n0 + nt * 8 + g;
            b[nt][0] = __float_as_uint(Wb[(k0 + tig) * LDS_W + c]);
            b[nt][1] = __float_as_uint(Wb[(k0 + tig + 4) * LDS_W + c]);
        }
        #pragma unroll
        for (int mt = 0; mt < 4; mt++)
            #pragma unroll
            for (int nt = 0; nt < 4; nt++)
                mma_tf32(acc[mt][nt], a[mt][0], a[mt][1], a[mt][2], a[mt][3],
                         b[nt][0], b[nt][1]);
    }
}

// issue cp.async for weight half h (0..15) into buffer (h&1)
__device__ __forceinline__ void issue_half(float* __restrict__ S, int h,
                                           const float* __restrict__ w1,
                                           const float* __restrict__ w2,
                                           int tid) {
    const int jc = h >> 2, sub = h & 3;
    const float* src;
    int ld, row0, col0;
    if (sub < 2) { src = w1; ld = H_DIM; row0 = sub * 64; col0 = jc * 128; }
    else         { src = w2; ld = F_DIM; row0 = jc * 128 + (sub - 2) * 64; col0 = 0; }
    float* Wb = S + WOFF + (h & 1) * WBUFSZ;
    const int r = tid >> 2;           // 0..63
    const int s0 = tid & 3;
    const float* gsrc = src + (long)(row0 + r) * ld + col0;
    const uint32_t sbase = smem_u32(Wb + r * LDS_W);
    #pragma unroll
    for (int it = 0; it < 8; it++) {
        const int seg = s0 + it * 4;  // 0..31
        cp_async16(sbase + seg * 16, gsrc + seg * 4);
    }
    CP_COMMIT();
}

// ---------------------------------------------------------------------------
// Kernel 3: fused main kernel. grid = (3, 384), 256 threads.
// ---------------------------------------------------------------------------
__global__ __launch_bounds__(NTHREADS, 1)
void k_main(const float* __restrict__ edge_vec,
            const float* __restrict__ b_out,
            const float* __restrict__ tr_scale,
            const float* __restrict__ tr_bias,
            const float* __restrict__ w_t1,
            const float* __restrict__ b_t1,
            const float* __restrict__ w_t2,
            const float* __restrict__ b_t2,
            float* __restrict__ out) {
    extern __shared__ float S[];
    const int tid = threadIdx.x;
    const int wid = tid >> 5;
    const int lane = tid & 31;
    const int g = lane >> 2;
    const int tig = lane & 3;
    const int a = blockIdx.y;
    const int bb = blockIdx.x * BM;

    float* s_scale = S + BOFF;
    float* s_bias  = S + BOFF + 128;
    float* s_b1    = S + BOFF + 256;
    float* s_b2    = S + BOFF + 768;
    float* s_bout  = S + BOFF + 896;

    // prefetch first two weight halves immediately
    issue_half(S, 0, w_t1, w_t2, tid);
    issue_half(S, 1, w_t1, w_t2, tid);

    // ---- stage biases, m_a + right (overlay in H region) ----
    for (int i = tid; i < F_DIM; i += NTHREADS) {
        s_scale[i] = tr_scale[i];
        s_bias[i]  = tr_bias[i];
        s_b2[i]    = b_t2[i];
        s_bout[i]  = b_out[i];
    }
    for (int i = tid; i < H_DIM; i += NTHREADS) s_b1[i] = b_t1[i];
    for (int idx = tid; idx < C_DIM * F_DIM; idx += NTHREADS)
        S[HOFF + idx] = g_M[a * C_DIM * F_DIM + idx];          // m_a[d][f]
    for (int idx = tid; idx < BM * C_DIM; idx += NTHREADS) {
        int r = idx >> 5, c = idx & 31;
        S[HOFF + 4096 + r * 33 + c] = g_right[(bb + r) * C_DIM + c];
    }
    __syncthreads();

    // ---- e = right @ M_a + edge + b_out (exact fp32) -> gmem out + LN tile ----
    {
        const int r0 = (tid >> 4) * 8;
        const int c0 = (tid & 15) * 8;
        float acc[8][8];
        #pragma unroll
        for (int i = 0; i < 8; i++)
            #pragma unroll
            for (int j = 0; j < 8; j++) acc[i][j] = 0.0f;

        #pragma unroll 4
        for (int k = 0; k < C_DIM; k++) {
            float4 bv0 = *reinterpret_cast<const float4*>(S + HOFF + k * 128 + c0);
            float4 bv1 = *reinterpret_cast<const float4*>(S + HOFF + k * 128 + c0 + 4);
            #pragma unroll
            for (int i = 0; i < 8; i++) {
                float av = S[HOFF + 4096 + (r0 + i) * 33 + k];
                acc[i][0] += av * bv0.x; acc[i][1] += av * bv0.y;
                acc[i][2] += av * bv0.z; acc[i][3] += av * bv0.w;
                acc[i][4] += av * bv1.x; acc[i][5] += av * bv1.y;
                acc[i][6] += av * bv1.z; acc[i][7] += av * bv1.w;
            }
        }
        const float* ep = edge_vec + ((long)(a * A_DIM) + bb) * F_DIM;
        float* op = out + ((long)(a * A_DIM) + bb) * F_DIM;
        #pragma unroll
        for (int i = 0; i < 8; i++) {
            const int r = r0 + i;
            #pragma unroll
            for (int jq = 0; jq < 2; jq++) {
                float4 e4 = *reinterpret_cast<const float4*>(ep + r * F_DIM + c0 + jq * 4);
                float4 o;
                o.x = acc[i][jq*4+0] + e4.x + s_bout[c0 + jq*4 + 0];
                o.y = acc[i][jq*4+1] + e4.y + s_bout[c0 + jq*4 + 1];
                o.z = acc[i][jq*4+2] + e4.z + s_bout[c0 + jq*4 + 2];
                o.w = acc[i][jq*4+3] + e4.w + s_bout[c0 + jq*4 + 3];
                *reinterpret_cast<float4*>(op + r * F_DIM + c0 + jq * 4) = o;
                *reinterpret_cast<float4*>(S + LNOFF + r * LDS_A + c0 + jq * 4) = o;
            }
        }
    }
    __syncthreads();

    // ---- layernorm rows in-place in LN tile (tf32-rounded output) ----
    {
        const int row = tid >> 1;
        const int half = tid & 1;
        float* er = S + LNOFF + row * LDS_A + half * 64;
        float sum = 0.0f, sq = 0.0f;
        #pragma unroll
        for (int q = 0; q < 16; q++) {
            float4 v = *reinterpret_cast<const float4*>(er + q * 4);
            sum += v.x + v.y + v.z + v.w;
            sq  += v.x*v.x + v.y*v.y + v.z*v.z + v.w*v.w;
        }
        sum += __shfl_xor_sync(~0u, sum, 1);
        sq  += __shfl_xor_sync(~0u, sq, 1);
        float mu = sum * (1.0f / F_DIM);
        float var = sq * (1.0f / F_DIM) - mu * mu;
        float rstd = rsqrtf(var + EPS);
        #pragma unroll
        for (int q = 0; q < 16; q++) {
            float4 v = *reinterpret_cast<const float4*>(er + q * 4);
            const int c = half * 64 + q * 4;
            float4 l;
            l.x = f2tf32f((v.x - mu) * rstd * s_scale[c+0] + s_bias[c+0]);
            l.y = f2tf32f((v.y - mu) * rstd * s_scale[c+1] + s_bias[c+1]);
            l.z = f2tf32f((v.z - mu) * rstd * s_scale[c+2] + s_bias[c+2]);
            l.w = f2tf32f((v.w - mu) * rstd * s_scale[c+3] + s_bias[c+3]);
            *reinterpret_cast<float4*>(er + q * 4) = l;
        }
    }
    __syncthreads();

    // ---- transition MLP: 16 weight halves, double-buffered ----
    const int m0 = (wid >> 2) * 64;
    const int n0 = (wid & 3) * 32;

    float oacc[4][4][4];
    #pragma unroll
    for (int mt = 0; mt < 4; mt++)
        #pragma unroll
        for (int nt = 0; nt < 4; nt++)
            #pragma unroll
            for (int q = 0; q < 4; q++) oacc[mt][nt][q] = 0.0f;

    #pragma unroll 1
    for (int jc = 0; jc < 4; jc++) {
        float hacc[4][4][4];
        #pragma unroll
        for (int mt = 0; mt < 4; mt++)
            #pragma unroll
            for (int nt = 0; nt < 4; nt++)
                #pragma unroll
                for (int q = 0; q < 4; q++) hacc[mt][nt][q] = 0.0f;

        const int h0 = jc * 4;
        // GEMM1 half 0
        CP_WAIT(1); __syncthreads();
        gemm_half(S + LNOFF, 0, S + WOFF + ((h0 + 0) & 1) * WBUFSZ, m0, n0, g, tig, hacc);
        __syncthreads();
        issue_half(S, h0 + 2, w_t1, w_t2, tid);
        // GEMM1 half 1
        CP_WAIT(1); __syncthreads();
        gemm_half(S + LNOFF, 64, S + WOFF + ((h0 + 1) & 1) * WBUFSZ, m0, n0, g, tig, hacc);
        __syncthreads();
        issue_half(S, h0 + 3, w_t1, w_t2, tid);

        // relu(H + b1) -> H tile (tf32)
        #pragma unroll
        for (int mt = 0; mt < 4; mt++) {
            const int r = m0 + mt * 16 + g;
            #pragma unroll
            for (int nt = 0; nt < 4; nt++) {
                const int c = n0 + nt * 8 + 2 * tig;
                const float bj0 = s_b1[jc * 128 + c];
                const float bj1 = s_b1[jc * 128 + c + 1];
                float2 v0, v1;
                v0.x = f2tf32f(fmaxf(hacc[mt][nt][0] + bj0, 0.0f));
                v0.y = f2tf32f(fmaxf(hacc[mt][nt][1] + bj1, 0.0f));
                v1.x = f2tf32f(fmaxf(hacc[mt][nt][2] + bj0, 0.0f));
                v1.y = f2tf32f(fmaxf(hacc[mt][nt][3] + bj1, 0.0f));
                *reinterpret_cast<float2*>(S + HOFF + r * LDS_A + c) = v0;
                *reinterpret_cast<float2*>(S + HOFF + (r + 8) * LDS_A + c) = v1;
            }
        }
        __syncthreads();

        // GEMM2 half 0
        CP_WAIT(1); __syncthreads();
        gemm_half(S + HOFF, 0, S + WOFF + ((h0 + 2) & 1) * WBUFSZ, m0, n0, g, tig, oacc);
        __syncthreads();
        if (h0 + 4 < 16) issue_half(S, h0 + 4, w_t1, w_t2, tid);
        // GEMM2 half 1
        if (h0 + 3 == 15) { CP_WAIT(0); } else { CP_WAIT(1); }
        __syncthreads();
        gemm_half(S + HOFF, 64, S + WOFF + ((h0 + 3) & 1) * WBUFSZ, m0, n0, g, tig, oacc);
        __syncthreads();
        if (h0 + 5 < 16) issue_half(S, h0 + 5, w_t1, w_t2, tid);
    }

    // ---- epilogue: out = e + O + b_t2 ----
    {
        float* op = out + ((long)(a * A_DIM) + bb) * F_DIM;
        #pragma unroll
        for (int mt = 0; mt < 4; mt++) {
            const int r = m0 + mt * 16 + g;
            #pragma unroll
            for (int nt = 0; nt < 4; nt++) {
                const int c = n0 + nt * 8 + 2 * tig;
                const float b20 = s_b2[c], b21 = s_b2[c + 1];
                float2 e0 = *reinterpret_cast<const float2*>(op + r * F_DIM + c);
                float2 e1 = *reinterpret_cast<const float2*>(op + (r + 8) * F_DIM + c);
                float2 o0, o1;
                o0.x = e0.x + oacc[mt][nt][0] + b20;
                o0.y = e0.y + oacc[mt][nt][1] + b21;
                o1.x = e1.x + oacc[mt][nt][2] + b20;
                o1.y = e1.y + oacc[mt][nt][3] + b21;
                *reinterpret_cast<float2*>(op + r * F_DIM + c) = o0;
                *reinterpret_cast<float2*>(op + (r + 8) * F_DIM + c) = o1;
            }
        }
    }
}

// ---------------------------------------------------------------------------
// Launch
// ---------------------------------------------------------------------------
extern "C" void kernel_launch(void* const* d_in, const int* in_sizes, int n_in,
                              void* d_out, int out_size) {
    const float* node_vec    = (const float*)d_in[0];
    const float* edge_vec    = (const float*)d_in[1];
    const float* node_mask   = (const float*)d_in[2];
    const float* op_ln_scale = (const float*)d_in[4];
    const float* op_ln_bias  = (const float*)d_in[5];
    const float* w_left      = (const float*)d_in[6];
    const float* b_left      = (const float*)d_in[7];
    const float* w_right     = (const float*)d_in[8];
    const float* b_right     = (const float*)d_in[9];
    const float* w_out       = (const float*)d_in[10];
    const float* b_out       = (const float*)d_in[11];
    const float* tr_ln_scale = (const float*)d_in[12];
    const float* tr_ln_bias  = (const float*)d_in[13];
    const float* w_t1        = (const float*)d_in[14];
    const float* b_t1        = (const float*)d_in[15];
    const float* w_t2        = (const float*)d_in[16];
    const float* b_t2        = (const float*)d_in[17];
    float* out = (float*)d_out;

    static bool attr_set = false;
    if (!attr_set) {
        cudaFuncSetAttribute(k_main, cudaFuncAttributeMaxDynamicSharedMemorySize,
                             (int)SMEM_BYTES);
        attr_set = true;
    }

    k_node<<<A_DIM, F_DIM>>>(node_vec, node_mask, op_ln_scale, op_ln_bias,
                             w_left, b_left, w_right, b_right);
    k_precompute_M<<<A_DIM, F_DIM>>>(w_out);
    k_main<<<dim3(A_DIM / BM, A_DIM), NTHREADS, SMEM_BYTES>>>(
        edge_vec, b_out, tr_ln_scale, tr_ln_bias,
        w_t1, b_t1, w_t2, b_t2, out);
}

// round 5
// speedup vs baseline: 5.6364x; 1.4536x over previous
#include <cuda_runtime.h>
#include <cuda_fp16.h>
#include <cstdint>

#define A_DIM 384
#define F_DIM 128
#define C_DIM 32
#define H_DIM 512
#define EPS 1e-5f
#define BM 128
#define NTHREADS 256

// smem byte offsets
#define A_LN_OFF 0
#define A_H_OFF  34816
#define WB0_OFF  69632
#define WB1_OFF  104448
#define BIAS_OFF 139264
#define SMEM_BYTES (139264 + 4096)
#define ROWB 272           // bytes per half row (136 halves)

// device scratch
__device__ float g_left[A_DIM * C_DIM];
__device__ float g_right[A_DIM * C_DIM];
__device__ float g_M[A_DIM * C_DIM * F_DIM];      // M[a][d][f]
__device__ __half g_w1h[F_DIM * H_DIM];           // [k=128][n=512]
__device__ __half g_w2h[H_DIM * F_DIM];           // [k=512][n=128]

__device__ __forceinline__ uint32_t smem_u32(const void* p) {
    uint32_t a;
    asm("{ .reg .u64 t; cvta.to.shared.u64 t, %1; cvt.u32.u64 %0, t; }" : "=r"(a) : "l"(p));
    return a;
}
__device__ __forceinline__ void cp_async16(uint32_t s, const void* g) {
    asm volatile("cp.async.ca.shared.global [%0], [%1], 16;" :: "r"(s), "l"(g));
}
#define CP_COMMIT() asm volatile("cp.async.commit_group;" ::: "memory")
#define CP_WAIT(n)  asm volatile("cp.async.wait_group %0;" :: "n"(n) : "memory")

__device__ __forceinline__ void ldsm4(uint32_t& r0, uint32_t& r1, uint32_t& r2,
                                      uint32_t& r3, uint32_t addr) {
    asm volatile("ldmatrix.sync.aligned.m8n8.x4.shared.b16 {%0,%1,%2,%3}, [%4];"
                 : "=r"(r0), "=r"(r1), "=r"(r2), "=r"(r3) : "r"(addr));
}
__device__ __forceinline__ void ldsm4t(uint32_t& r0, uint32_t& r1, uint32_t& r2,
                                       uint32_t& r3, uint32_t addr) {
    asm volatile("ldmatrix.sync.aligned.m8n8.x4.trans.shared.b16 {%0,%1,%2,%3}, [%4];"
                 : "=r"(r0), "=r"(r1), "=r"(r2), "=r"(r3) : "r"(addr));
}
__device__ __forceinline__ void mma_f16(float c[4], uint32_t a0, uint32_t a1,
                                        uint32_t a2, uint32_t a3,
                                        uint32_t b0, uint32_t b1) {
    asm volatile(
        "mma.sync.aligned.m16n8k16.row.col.f32.f16.f16.f32 "
        "{%0,%1,%2,%3}, {%4,%5,%6,%7}, {%8,%9}, {%0,%1,%2,%3};"
        : "+f"(c[0]), "+f"(c[1]), "+f"(c[2]), "+f"(c[3])
        : "r"(a0), "r"(a1), "r"(a2), "r"(a3), "r"(b0), "r"(b1));
}

// ---------------------------------------------------------------------------
// Kernel 1: node LN -> left/right (masked); also fp32->fp16 weight convert.
// 384 blocks x 128 threads.
// ---------------------------------------------------------------------------
__global__ void k_pre(const float* __restrict__ node_vec,
                      const float* __restrict__ node_mask,
                      const float* __restrict__ ln_scale,
                      const float* __restrict__ ln_bias,
                      const float* __restrict__ w_left,
                      const float* __restrict__ b_left,
                      const float* __restrict__ w_right,
                      const float* __restrict__ b_right,
                      const float* __restrict__ w_t1,
                      const float* __restrict__ w_t2) {
    int a = blockIdx.x;
    int t = threadIdx.x;
    __shared__ float act[F_DIM];
    __shared__ float red[4];

    // weight cvt (spread over grid)
    for (int idx = a * 128 + t; idx < 131072; idx += 384 * 128) {
        if (idx < 65536) g_w1h[idx] = __float2half_rn(w_t1[idx]);
        else             g_w2h[idx - 65536] = __float2half_rn(w_t2[idx - 65536]);
    }

    float x = node_vec[a * F_DIM + t];
    float s = x;
    #pragma unroll
    for (int o = 16; o; o >>= 1) s += __shfl_xor_sync(~0u, s, o);
    if ((t & 31) == 0) red[t >> 5] = s;
    __syncthreads();
    float mu = (red[0] + red[1] + red[2] + red[3]) * (1.0f / F_DIM);
    __syncthreads();
    float d = x - mu;
    float s2 = d * d;
    #pragma unroll
    for (int o = 16; o; o >>= 1) s2 += __shfl_xor_sync(~0u, s2, o);
    if ((t & 31) == 0) red[t >> 5] = s2;
    __syncthreads();
    float var = (red[0] + red[1] + red[2] + red[3]) * (1.0f / F_DIM);
    float rstd = rsqrtf(var + EPS);
    act[t] = d * rstd * ln_scale[t] + ln_bias[t];
    __syncthreads();

    float nm = node_mask[a];
    if (t < C_DIM) {
        float acc = b_left[t];
        #pragma unroll 8
        for (int f = 0; f < F_DIM; f++) acc += act[f] * w_left[f * C_DIM + t];
        g_left[a * C_DIM + t] = acc * nm;
    } else if (t < 2 * C_DIM) {
        int c = t - C_DIM;
        float acc = b_right[c];
        #pragma unroll 8
        for (int f = 0; f < F_DIM; f++) acc += act[f] * w_right[f * C_DIM + c];
        g_right[a * C_DIM + c] = acc * nm;
    }
}

// ---------------------------------------------------------------------------
// Kernel 2: M[a][d][f] = sum_c left[a,c] * w_out[(c*32+d)*128 + f]
// 48 blocks x 512 threads; each block covers 8 a's, reads w_out once.
// ---------------------------------------------------------------------------
__global__ __launch_bounds__(512)
void k_M(const float* __restrict__ w_out) {
    int a0 = blockIdx.x * 8;
    int tid = threadIdx.x;
    int f = tid & 127;
    int d0 = (tid >> 7) * 8;
    __shared__ float s_left[8][C_DIM];
    if (tid < 256) s_left[tid >> 5][tid & 31] = g_left[(a0 + (tid >> 5)) * C_DIM + (tid & 31)];
    __syncthreads();

    float acc[8][8];
    #pragma unroll
    for (int i = 0; i < 8; i++)
        #pragma unroll
        for (int j = 0; j < 8; j++) acc[i][j] = 0.0f;

    for (int c = 0; c < C_DIM; c++) {
        float w[8];
        #pragma unroll
        for (int j = 0; j < 8; j++)
            w[j] = w_out[(c * C_DIM + d0 + j) * F_DIM + f];
        #pragma unroll
        for (int i = 0; i < 8; i++) {
            float lv = s_left[i][c];
            #pragma unroll
            for (int j = 0; j < 8; j++) acc[i][j] += lv * w[j];
        }
    }
    #pragma unroll
    for (int i = 0; i < 8; i++)
        #pragma unroll
        for (int j = 0; j < 8; j++)
            g_M[((a0 + i) * C_DIM + d0 + j) * F_DIM + f] = acc[i][j];
}

// ---------------------------------------------------------------------------
// cp.async one 128x128 fp16 weight chunk ci (0..7) into its buffer (ci&1).
// ci even -> W1 chunk jc=ci>>1; ci odd -> W2 chunk jc=ci>>1.
// ---------------------------------------------------------------------------
__device__ __forceinline__ void issue_chunk(char* smem, int ci, int tid) {
    const int jc = ci >> 1;
    const __half* src;
    int ld;
    if ((ci & 1) == 0) { src = g_w1h + jc * 128; ld = H_DIM; }
    else               { src = g_w2h + jc * 128 * F_DIM; ld = F_DIM; }
    const uint32_t wb = smem_u32(smem + ((ci & 1) ? WB1_OFF : WB0_OFF));
    const int r = tid >> 1;
    const int s0 = (tid & 1) * 8;
    const __half* gsrc = src + (long)r * ld;
    const uint32_t dst = wb + r * ROWB + s0 * 16;
    #pragma unroll
    for (int s = 0; s < 8; s++)
        cp_async16(dst + s * 16, gsrc + (s0 + s) * 8);
    CP_COMMIT();
}

// ---------------------------------------------------------------------------
// One 128x128x128 chunk GEMM: acc += A[128,128] @ W[128,128] (fp16 in, f32 acc)
// ---------------------------------------------------------------------------
__device__ __forceinline__ void gemm_chunk(uint32_t Abase, uint32_t Wbase,
                                           int lane, int m0, int n0,
                                           float (&acc)[4][4][4]) {
    const uint32_t a_off = Abase + (uint32_t)(m0 + (lane & 15)) * ROWB + (lane >> 4) * 16;
    const uint32_t b_row = ((lane >> 3) & 1) * 8 + (lane & 7);
    const uint32_t b_off = Wbase + b_row * ROWB + (uint32_t)n0 * 2 + (lane >> 4) * 16;

    #pragma unroll
    for (int ks = 0; ks < 8; ks++) {
        const uint32_t k0 = ks * 16;
        uint32_t a[4][4];
        #pragma unroll
        for (int mt = 0; mt < 4; mt++)
            ldsm4(a[mt][0], a[mt][1], a[mt][2], a[mt][3],
                  a_off + mt * 16 * ROWB + k0 * 2);
        uint32_t b[4][2];
        #pragma unroll
        for (int nq = 0; nq < 2; nq++) {
            uint32_t r0, r1, r2, r3;
            ldsm4t(r0, r1, r2, r3, b_off + k0 * ROWB + nq * 32);
            b[nq * 2][0] = r0; b[nq * 2][1] = r1;
            b[nq * 2 + 1][0] = r2; b[nq * 2 + 1][1] = r3;
        }
        #pragma unroll
        for (int mt = 0; mt < 4; mt++)
            #pragma unroll
            for (int nb = 0; nb < 4; nb++)
                mma_f16(acc[mt][nb], a[mt][0], a[mt][1], a[mt][2], a[mt][3],
                        b[nb][0], b[nb][1]);
    }
}

// ---------------------------------------------------------------------------
// Kernel 3: fused main kernel. grid = (3, 384), 256 threads.
// ---------------------------------------------------------------------------
__global__ __launch_bounds__(NTHREADS, 1)
void k_main(const float* __restrict__ edge_vec,
            const float* __restrict__ b_out,
            const float* __restrict__ tr_scale,
            const float* __restrict__ tr_bias,
            const float* __restrict__ b_t1,
            const float* __restrict__ b_t2,
            float* __restrict__ out) {
    extern __shared__ char smem[];
    const int tid = threadIdx.x;
    const int wid = tid >> 5;
    const int lane = tid & 31;
    const int a = blockIdx.y;
    const int bb = blockIdx.x * BM;

    // prefetch first two weight chunks
    issue_chunk(smem, 0, tid);
    issue_chunk(smem, 1, tid);

    float* s_bias32 = (float*)(smem + BIAS_OFF);
    float* s_scale = s_bias32;          // [0:128)
    float* s_bias  = s_bias32 + 128;    // [128:256)
    float* s_b1    = s_bias32 + 256;    // [256:768)
    float* s_b2    = s_bias32 + 768;    // [768:896)
    float* s_bout  = s_bias32 + 896;    // [896:1024)
    for (int i = tid; i < F_DIM; i += NTHREADS) {
        s_scale[i] = tr_scale[i];
        s_bias[i]  = tr_bias[i];
        s_b2[i]    = b_t2[i];
        s_bout[i]  = b_out[i];
    }
    for (int i = tid; i < H_DIM; i += NTHREADS) s_b1[i] = b_t1[i];

    // stage m_a + right into A_H region (as fp32 overlay)
    float* Sf = (float*)(smem + A_H_OFF);
    for (int idx = tid; idx < C_DIM * F_DIM; idx += NTHREADS)
        Sf[idx] = g_M[a * C_DIM * F_DIM + idx];               // m_a[d][f]
    for (int idx = tid; idx < BM * C_DIM; idx += NTHREADS) {
        int r = idx >> 5, c = idx & 31;
        Sf[4096 + r * 33 + c] = g_right[(bb + r) * C_DIM + c];
    }
    __syncthreads();

    // ---- e = right @ M_a + edge + b_out (fp32) -> gmem; fused LN -> A_LN fp16
    {
        const int ty = tid >> 4, tx = tid & 15;
        const int r0 = ty * 8, c0 = tx * 8;
        float acc[8][8];
        #pragma unroll
        for (int i = 0; i < 8; i++)
            #pragma unroll
            for (int j = 0; j < 8; j++) acc[i][j] = 0.0f;

        #pragma unroll 4
        for (int k = 0; k < C_DIM; k++) {
            float4 bv0 = *reinterpret_cast<const float4*>(Sf + k * 128 + c0);
            float4 bv1 = *reinterpret_cast<const float4*>(Sf + k * 128 + c0 + 4);
            #pragma unroll
            for (int i = 0; i < 8; i++) {
                float av = Sf[4096 + (r0 + i) * 33 + k];
                acc[i][0] += av * bv0.x; acc[i][1] += av * bv0.y;
                acc[i][2] += av * bv0.z; acc[i][3] += av * bv0.w;
                acc[i][4] += av * bv1.x; acc[i][5] += av * bv1.y;
                acc[i][6] += av * bv1.z; acc[i][7] += av * bv1.w;
            }
        }
        const float* ep = edge_vec + ((long)(a * A_DIM) + bb) * F_DIM;
        float* op = out + ((long)(a * A_DIM) + bb) * F_DIM;
        float rs[8], rq[8];
        #pragma unroll
        for (int i = 0; i < 8; i++) {
            const int r = r0 + i;
            float4 e0 = *reinterpret_cast<const float4*>(ep + r * F_DIM + c0);
            float4 e1 = *reinterpret_cast<const float4*>(ep + r * F_DIM + c0 + 4);
            acc[i][0] += e0.x + s_bout[c0+0]; acc[i][1] += e0.y + s_bout[c0+1];
            acc[i][2] += e0.z + s_bout[c0+2]; acc[i][3] += e0.w + s_bout[c0+3];
            acc[i][4] += e1.x + s_bout[c0+4]; acc[i][5] += e1.y + s_bout[c0+5];
            acc[i][6] += e1.z + s_bout[c0+6]; acc[i][7] += e1.w + s_bout[c0+7];
            float4 o0 = make_float4(acc[i][0], acc[i][1], acc[i][2], acc[i][3]);
            float4 o1 = make_float4(acc[i][4], acc[i][5], acc[i][6], acc[i][7]);
            *reinterpret_cast<float4*>(op + r * F_DIM + c0) = o0;
            *reinterpret_cast<float4*>(op + r * F_DIM + c0 + 4) = o1;
            float s = 0.0f, q = 0.0f;
            #pragma unroll
            for (int j = 0; j < 8; j++) { s += acc[i][j]; q += acc[i][j] * acc[i][j]; }
            rs[i] = s; rq[i] = q;
        }
        // reduce across the 16 threads sharing these rows
        #pragma unroll
        for (int off = 1; off < 16; off <<= 1) {
            #pragma unroll
            for (int i = 0; i < 8; i++) {
                rs[i] += __shfl_xor_sync(~0u, rs[i], off);
                rq[i] += __shfl_xor_sync(~0u, rq[i], off);
            }
        }
        #pragma unroll
        for (int i = 0; i < 8; i++) {
            const float mu = rs[i] * (1.0f / F_DIM);
            const float var = rq[i] * (1.0f / F_DIM) - mu * mu;
            const float rstd = rsqrtf(var + EPS);
            __half2 h[4];
            #pragma unroll
            for (int jq = 0; jq < 4; jq++) {
                float l0 = (acc[i][jq*2+0] - mu) * rstd * s_scale[c0+jq*2+0] + s_bias[c0+jq*2+0];
                float l1 = (acc[i][jq*2+1] - mu) * rstd * s_scale[c0+jq*2+1] + s_bias[c0+jq*2+1];
                h[jq] = __floats2half2_rn(l0, l1);
            }
            *reinterpret_cast<uint4*>(smem + A_LN_OFF + (r0 + i) * ROWB + c0 * 2) =
                *reinterpret_cast<uint4*>(h);
        }
    }
    __syncthreads();

    // ---- transition MLP: 4 j-chunks ----
    const int m0 = (wid >> 2) * 64;
    const int n0 = (wid & 3) * 32;
    const int g = lane >> 2, tig = lane & 3;
    const uint32_t Aln = smem_u32(smem + A_LN_OFF);
    const uint32_t Ah  = smem_u32(smem + A_H_OFF);
    const uint32_t Wb0 = smem_u32(smem + WB0_OFF);
    const uint32_t Wb1 = smem_u32(smem + WB1_OFF);

    float oacc[4][4][4];
    #pragma unroll
    for (int mt = 0; mt < 4; mt++)
        #pragma unroll
        for (int nb = 0; nb < 4; nb++)
            #pragma unroll
            for (int q = 0; q < 4; q++) oacc[mt][nb][q] = 0.0f;

    #pragma unroll 1
    for (int jc = 0; jc < 4; jc++) {
        float hacc[4][4][4];
        #pragma unroll
        for (int mt = 0; mt < 4; mt++)
            #pragma unroll
            for (int nb = 0; nb < 4; nb++)
                #pragma unroll
                for (int q = 0; q < 4; q++) hacc[mt][nb][q] = 0.0f;

        CP_WAIT(1);
        __syncthreads();
        gemm_chunk(Aln, Wb0, lane, m0, n0, hacc);     // GEMM1 on W1 chunk jc
        __syncthreads();
        if (jc < 3) issue_chunk(smem, 2 * jc + 2, tid);

        // relu(H + b1) -> A_H fp16
        #pragma unroll
        for (int mt = 0; mt < 4; mt++) {
            const int r = m0 + mt * 16 + g;
            #pragma unroll
            for (int nb = 0; nb < 4; nb++) {
                const int c = n0 + nb * 8 + 2 * tig;
                const float b0 = s_b1[jc * 128 + c];
                const float b1 = s_b1[jc * 128 + c + 1];
                __half2 v0 = __floats2half2_rn(fmaxf(hacc[mt][nb][0] + b0, 0.0f),
                                               fmaxf(hacc[mt][nb][1] + b1, 0.0f));
                __half2 v1 = __floats2half2_rn(fmaxf(hacc[mt][nb][2] + b0, 0.0f),
                                               fmaxf(hacc[mt][nb][3] + b1, 0.0f));
                *reinterpret_cast<__half2*>(smem + A_H_OFF + r * ROWB + c * 2) = v0;
                *reinterpret_cast<__half2*>(smem + A_H_OFF + (r + 8) * ROWB + c * 2) = v1;
            }
        }
        if (jc < 3) { CP_WAIT(1); } else { CP_WAIT(0); }
        __syncthreads();
        gemm_chunk(Ah, Wb1, lane, m0, n0, oacc);      // GEMM2 on W2 chunk jc
        __syncthreads();
        if (jc < 3) issue_chunk(smem, 2 * jc + 3, tid);
    }

    // ---- epilogue: out = e + O + b_t2 ----
    {
        float* op = out + ((long)(a * A_DIM) + bb) * F_DIM;
        #pragma unroll
        for (int mt = 0; mt < 4; mt++) {
            const int r = m0 + mt * 16 + g;
            #pragma unroll
            for (int nb = 0; nb < 4; nb++) {
                const int c = n0 + nb * 8 + 2 * tig;
                const float b20 = s_b2[c], b21 = s_b2[c + 1];
                float2 e0 = *reinterpret_cast<const float2*>(op + r * F_DIM + c);
                float2 e1 = *reinterpret_cast<const float2*>(op + (r + 8) * F_DIM + c);
                float2 o0, o1;
                o0.x = e0.x + oacc[mt][nb][0] + b20;
                o0.y = e0.y + oacc[mt][nb][1] + b21;
                o1.x = e1.x + oacc[mt][nb][2] + b20;
                o1.y = e1.y + oacc[mt][nb][3] + b21;
                *reinterpret_cast<float2*>(op + r * F_DIM + c) = o0;
                *reinterpret_cast<float2*>(op + (r + 8) * F_DIM + c) = o1;
            }
        }
    }
}

// ---------------------------------------------------------------------------
// Launch
// ---------------------------------------------------------------------------
extern "C" void kernel_launch(void* const* d_in, const int* in_sizes, int n_in,
                              void* d_out, int out_size) {
    const float* node_vec    = (const float*)d_in[0];
    const float* edge_vec    = (const float*)d_in[1];
    const float* node_mask   = (const float*)d_in[2];
    const float* op_ln_scale = (const float*)d_in[4];
    const float* op_ln_bias  = (const float*)d_in[5];
    const float* w_left      = (const float*)d_in[6];
    const float* b_left      = (const float*)d_in[7];
    const float* w_right     = (const float*)d_in[8];
    const float* b_right     = (const float*)d_in[9];
    const float* w_out       = (const float*)d_in[10];
    const float* b_out       = (const float*)d_in[11];
    const float* tr_ln_scale = (const float*)d_in[12];
    const float* tr_ln_bias  = (const float*)d_in[13];
    const float* w_t1        = (const float*)d_in[14];
    const float* b_t1        = (const float*)d_in[15];
    const float* w_t2        = (const float*)d_in[16];
    const float* b_t2        = (const float*)d_in[17];
    float* out = (float*)d_out;

    static bool attr_set = false;
    if (!attr_set) {
        cudaFuncSetAttribute(k_main, cudaFuncAttributeMaxDynamicSharedMemorySize,
                             (int)SMEM_BYTES);
        attr_set = true;
    }

    k_pre<<<A_DIM, F_DIM>>>(node_vec, node_mask, op_ln_scale, op_ln_bias,
                            w_left, b_left, w_right, b_right, w_t1, w_t2);
    k_M<<<A_DIM / 8, 512>>>(w_out);
    k_main<<<dim3(A_DIM / BM, A_DIM), NTHREADS, SMEM_BYTES>>>(
        edge_vec, b_out, tr_ln_scale, tr_ln_bias, b_t1, b_t2, out);
}